// round 3
// baseline (speedup 1.0000x reference)
#include <cuda_runtime.h>

// Locally connected 2D, f32x2-packed version.
//   y[n,h,w] = relu( sum_{i,j} x[n,h+i,w+j] * W[h,w,i,j] + b[h,w] )
// N=64, H_IN=W_IN=512, K=9, H_OUT=W_OUT=504.
//
// Each lane carries TWO batch images packed in a 64-bit reg (n=lane, n=lane+32),
// so one warp covers all 64 batches and fma.rn.f32x2 does 2 MACs/issue.
// Weights are stored DUPLICATED {w,w} in smem so LDS.128 yields two packed
// weight operands directly (no per-use packing).
//
// CTA: 256 threads = 8 warps = 4 h-rows x 2 w-halves. Tile: 4h x 12w x 64n.
// Exact tiling: 504 = 42*12 = 126*4. No boundary predicates.

#define TW 12            // w outputs per CTA row
#define WH 6             // w outputs per warp (half)
#define TH 4             // h rows per CTA
#define XC (TW + 8)      // 20 x cols staged
#define XR (TH + 8)      // 12 x rows staged
#define XPITCH 66        // floats per (r,c) cell: 32 pairs*2 + 2 pad (bank-safe)
#define WROW 20          // floats per (pix,i) row: 9 dup-pairs (18) + 2 pad
#define PIX (TH * TW)    // 48 pixels per CTA

// smem layout (floats):
//   XS: [XR*XC][XPITCH]  = 240*66 = 15840   (XS[(r*20+c)*66 + lane*2 + half])
//   WS: [PIX][9][WROW]   = 48*180 =  8640   (dup pairs, 16B-aligned rows)
#define XS_OFF 0
#define WS_OFF (XR * XC * XPITCH)            // 15840
#define SMEM_FLOATS (WS_OFF + PIX * 9 * WROW) // 24480
#define SMEM_BYTES (SMEM_FLOATS * 4)          // 97920

typedef unsigned long long u64;

__device__ __forceinline__ u64 ffma2(u64 a, u64 b, u64 c) {
    u64 d;
    asm("fma.rn.f32x2 %0, %1, %2, %3;" : "=l"(d) : "l"(a), "l"(b), "l"(c));
    return d;
}
__device__ __forceinline__ void unpack2(u64 v, float& lo, float& hi) {
    asm("mov.b64 {%0, %1}, %2;" : "=f"(lo), "=f"(hi) : "l"(v));
}

__global__ __launch_bounds__(256, 2)
void lc2d_kernel(const float* __restrict__ x,
                 const float* __restrict__ wgt,
                 const float* __restrict__ bias,
                 float* __restrict__ out)
{
    extern __shared__ float sm[];
    float* XS = sm + XS_OFF;
    float* WS = sm + WS_OFF;

    const int tid  = threadIdx.x;
    const int lane = tid & 31;
    const int warp = tid >> 5;

    const int w0 = blockIdx.x * TW;   // 0..492
    const int h0 = blockIdx.y * TH;   // 0..500

    // ---- stage x: x[n, h0+r, w0+c] -> XS[(r*20+c)*66 + (n&31)*2 + (n>>5)] ----
    // flat t = n*240 + r*20 + c : consecutive tids -> consecutive c (coalesced LDG).
    {
        const float* xb = x + (size_t)h0 * 512 + w0;
        for (int t = tid; t < 64 * XR * XC; t += 256) {
            int n   = t / (XR * XC);
            int rem = t - n * (XR * XC);
            int r   = rem / XC;
            int c   = rem - r * XC;
            XS[(r * XC + c) * XPITCH + (n & 31) * 2 + (n >> 5)] =
                xb[(size_t)n * (512 * 512) + r * 512 + c];
        }
    }

    // ---- stage weights duplicated: W[pix, i, j] -> WS[pix*180 + i*20 + 2j] (x2) ----
    {
        for (int t = tid; t < PIX * 81; t += 256) {
            int pix = t / 81;
            int q   = t - pix * 81;
            int i   = q / 9;
            int j   = q - i * 9;
            int hl  = pix / TW;
            int o   = pix - hl * TW;
            float w = wgt[((size_t)(h0 + hl) * 504 + (w0 + o)) * 81 + q];
            float2* dst = reinterpret_cast<float2*>(&WS[pix * (9 * WROW) + i * WROW + 2 * j]);
            *dst = make_float2(w, w);   // STS.64, conflict-free
        }
    }

    __syncthreads();

    // ---- compute: warp = (hl, wh); lane packs batches (lane, lane+32) ----
    const int hl = warp >> 1;         // 0..3
    const int wh = warp & 1;          // 0..1
    const int h  = h0 + hl;
    const int cbase = wh * WH;        // 0 or 6

    u64 acc[WH];
#pragma unroll
    for (int o = 0; o < WH; o++) acc[o] = 0ull;

    const float* wbase = &WS[(hl * TW + cbase) * (9 * WROW)];

#pragma unroll
    for (int i = 0; i < 9; i++) {
        const int r = hl + i;
        // sliding x window: 14 packed values (LDS.64, conflict-free)
        u64 xw[WH + 8];
        const float* xrow = &XS[(r * XC + cbase) * XPITCH + lane * 2];
#pragma unroll
        for (int c = 0; c < WH + 8; c++)
            xw[c] = *reinterpret_cast<const u64*>(xrow + c * XPITCH);

#pragma unroll
        for (int o = 0; o < WH; o++) {
            const float* wrow = wbase + o * (9 * WROW) + i * WROW;
            const ulonglong2 w01 = *reinterpret_cast<const ulonglong2*>(wrow);       // pairs 0,1
            const ulonglong2 w23 = *reinterpret_cast<const ulonglong2*>(wrow + 4);   // pairs 2,3
            const ulonglong2 w45 = *reinterpret_cast<const ulonglong2*>(wrow + 8);   // pairs 4,5
            const ulonglong2 w67 = *reinterpret_cast<const ulonglong2*>(wrow + 12);  // pairs 6,7
            const u64        w8  = *reinterpret_cast<const u64*>(wrow + 16);         // pair 8
            u64 a = acc[o];
            a = ffma2(xw[o + 0], w01.x, a);
            a = ffma2(xw[o + 1], w01.y, a);
            a = ffma2(xw[o + 2], w23.x, a);
            a = ffma2(xw[o + 3], w23.y, a);
            a = ffma2(xw[o + 4], w45.x, a);
            a = ffma2(xw[o + 5], w45.y, a);
            a = ffma2(xw[o + 6], w67.x, a);
            a = ffma2(xw[o + 7], w67.y, a);
            a = ffma2(xw[o + 8], w8,    a);
            acc[o] = a;
        }
    }

    // ---- bias + relu + direct store (3x STG.64 per batch) ----
    {
        const float* bp = bias + (size_t)h * 504 + w0 + cbase;
        float lo[WH], hi[WH];
#pragma unroll
        for (int o = 0; o < WH; o++) {
            float l, hgh;
            unpack2(acc[o], l, hgh);
            const float b = __ldg(bp + o);
            lo[o] = fmaxf(l + b, 0.0f);
            hi[o] = fmaxf(hgh + b, 0.0f);
        }
        float* d0 = out + ((size_t)lane        * 504 + h) * 504 + w0 + cbase;
        float* d1 = out + ((size_t)(lane + 32) * 504 + h) * 504 + w0 + cbase;
        reinterpret_cast<float2*>(d0)[0] = make_float2(lo[0], lo[1]);
        reinterpret_cast<float2*>(d0)[1] = make_float2(lo[2], lo[3]);
        reinterpret_cast<float2*>(d0)[2] = make_float2(lo[4], lo[5]);
        reinterpret_cast<float2*>(d1)[0] = make_float2(hi[0], hi[1]);
        reinterpret_cast<float2*>(d1)[1] = make_float2(hi[2], hi[3]);
        reinterpret_cast<float2*>(d1)[2] = make_float2(hi[4], hi[5]);
    }
}

extern "C" void kernel_launch(void* const* d_in, const int* in_sizes, int n_in,
                              void* d_out, int out_size)
{
    const float* x    = (const float*)d_in[0];
    const float* wgt  = (const float*)d_in[1];
    const float* bias = (const float*)d_in[2];
    float* out        = (float*)d_out;

    cudaFuncSetAttribute(lc2d_kernel,
                         cudaFuncAttributeMaxDynamicSharedMemorySize,
                         SMEM_BYTES);

    dim3 grid(504 / TW, 504 / TH);   // 42 x 126 = 5292 CTAs
    lc2d_kernel<<<grid, 256, SMEM_BYTES>>>(x, wgt, bias, out);
}

// round 4
// speedup vs baseline: 1.9691x; 1.9691x over previous
#include <cuda_runtime.h>

// Locally connected 2D:
//   y[n,h,w] = relu( sum_{i,j} x[n,h+i,w+j] * W[h,w,i,j] + b[h,w] )
// N=64, H_IN=W_IN=512, K=9, H_OUT=W_OUT=504.
//
// CTA: 512 threads = 16 warps = 4 h-rows x 2 n-halves x 2 w-halves.
// Tile: 4h x 12w x 64n (exact: 504 = 42*12 = 126*4). Lanes carry batch n,
// so weight LDS is warp-uniform broadcast. x staged [r][n][c] with col pitch
// 20 -> the per-lane sliding window is 4x LDS.128 (conflict-free: lane
// stride 20 floats = 80B gives distinct 16B bank groups per quarter-warp).

#define TW 12            // w outputs per CTA
#define WH 6             // w outputs per thread (w-half)
#define TH 4             // h rows per CTA
#define XR (TH + 8)      // 12 x rows staged
#define CP 20            // x cols staged per n (col pitch, floats)
#define RSTRIDE (64 * CP + 4)   // 1284 floats: +4 pad de-conflicts staging STS
#define WROW 12          // 9 taps padded to 12 floats (48B, 16B-aligned)
#define PIX (TH * TW)    // 48 pixels per CTA

// smem (floats): XS[XR][RSTRIDE] = 15408 ; WS[PIX][9*WROW] = 5184
#define XS_OFF 0
#define WS_OFF (XR * RSTRIDE)                 // 15408
#define SMEM_FLOATS (WS_OFF + PIX * 9 * WROW) // 20592
#define SMEM_BYTES (SMEM_FLOATS * 4)          // 82368

__global__ __launch_bounds__(512, 2)
void lc2d_kernel(const float* __restrict__ x,
                 const float* __restrict__ wgt,
                 const float* __restrict__ bias,
                 float* __restrict__ out)
{
    extern __shared__ float sm[];
    float* XS = sm + XS_OFF;
    float* WS = sm + WS_OFF;

    const int tid  = threadIdx.x;
    const int lane = tid & 31;
    const int warp = tid >> 5;

    const int w0 = blockIdx.x * TW;   // 0..492
    const int h0 = blockIdx.y * TH;   // 0..500

    // ---- stage x: x[n, h0+r, w0+4c4 .. +3] -> XS[r*RSTRIDE + n*CP + 4c4] ----
    // 64 n * 12 r * 5 float4 = 3840 f4 over 512 threads; structured, no big
    // div/mod. 8 threads per n, each covers item m = s + 8k (m < 60).
    {
        const int n = tid >> 3;        // 0..63
        const int s = tid & 7;
        const float* src = x + (size_t)n * (512 * 512) + (size_t)h0 * 512 + w0;
        float* dstn = XS + n * CP;
#pragma unroll
        for (int k = 0; k < 8; k++) {
            int m = s + 8 * k;         // 0..63
            if (m < 60) {
                int r  = m / 5;        // small-const div -> IMAD
                int c4 = m - r * 5;
                float4 v = *reinterpret_cast<const float4*>(src + r * 512 + c4 * 4);
                *reinterpret_cast<float4*>(dstn + r * RSTRIDE + c4 * 4) = v;
            }
        }
    }

    // ---- stage weights: W[h0+hl, w0+o, i, j] -> WS[pix*108 + i*12 + j] ----
    {
        for (int t = tid; t < PIX * 81; t += 512) {   // 8 iterations
            int pix = t / 81;
            int q   = t - pix * 81;
            int i   = q / 9;
            int j   = q - i * 9;
            int hl  = pix / TW;
            int o   = pix - hl * TW;
            WS[pix * (9 * WROW) + i * WROW + j] =
                wgt[((size_t)(h0 + hl) * 504 + (w0 + o)) * 81 + q];
        }
    }

    __syncthreads();

    // ---- compute: warp = (hl, nh, wh); lane = n within half ----
    const int hl = warp >> 2;          // 0..3
    const int nh = (warp >> 1) & 1;    // 0..1
    const int wh = warp & 1;           // 0..1
    const int n  = nh * 32 + lane;
    const int h  = h0 + hl;
    const int cbase = wh * WH;         // 0 or 6
    const int xoff  = 2 * wh;          // window index offset into xw[16]

    float acc[WH];
#pragma unroll
    for (int o = 0; o < WH; o++) acc[o] = 0.0f;

    const float* wbase = &WS[(hl * TW + cbase) * (9 * WROW)];

#pragma unroll
    for (int i = 0; i < 9; i++) {
        const int r = hl + i;
        // 16-col window via 4x LDS.128 (wh=0: cols 0..15; wh=1: cols 4..19)
        const float* xrow = XS + r * RSTRIDE + n * CP + wh * 4;
        float4 X0 = reinterpret_cast<const float4*>(xrow)[0];
        float4 X1 = reinterpret_cast<const float4*>(xrow)[1];
        float4 X2 = reinterpret_cast<const float4*>(xrow)[2];
        float4 X3 = reinterpret_cast<const float4*>(xrow)[3];
        float xw[16] = { X0.x, X0.y, X0.z, X0.w,
                         X1.x, X1.y, X1.z, X1.w,
                         X2.x, X2.y, X2.z, X2.w,
                         X3.x, X3.y, X3.z, X3.w };

#pragma unroll
        for (int o = 0; o < WH; o++) {
            const float* wrow = wbase + o * (9 * WROW) + i * WROW;
            const float4 wa = reinterpret_cast<const float4*>(wrow)[0]; // broadcast
            const float4 wb = reinterpret_cast<const float4*>(wrow)[1]; // broadcast
            const float  w8 = wrow[8];
            const int b = xoff + o;
            float a = acc[o];
            a = fmaf(xw[b + 0], wa.x, a);
            a = fmaf(xw[b + 1], wa.y, a);
            a = fmaf(xw[b + 2], wa.z, a);
            a = fmaf(xw[b + 3], wa.w, a);
            a = fmaf(xw[b + 4], wb.x, a);
            a = fmaf(xw[b + 5], wb.y, a);
            a = fmaf(xw[b + 6], wb.z, a);
            a = fmaf(xw[b + 7], wb.w, a);
            a = fmaf(xw[b + 8], w8,   a);
            acc[o] = a;
        }
    }

    // ---- bias + relu + direct store (3x STG.64) ----
    {
        const float* bp = bias + (size_t)h * 504 + w0 + cbase;
        float* dst = out + ((size_t)n * 504 + h) * 504 + w0 + cbase;
        float r0 = fmaxf(acc[0] + __ldg(bp + 0), 0.0f);
        float r1 = fmaxf(acc[1] + __ldg(bp + 1), 0.0f);
        float r2 = fmaxf(acc[2] + __ldg(bp + 2), 0.0f);
        float r3 = fmaxf(acc[3] + __ldg(bp + 3), 0.0f);
        float r4 = fmaxf(acc[4] + __ldg(bp + 4), 0.0f);
        float r5 = fmaxf(acc[5] + __ldg(bp + 5), 0.0f);
        reinterpret_cast<float2*>(dst)[0] = make_float2(r0, r1);
        reinterpret_cast<float2*>(dst)[1] = make_float2(r2, r3);
        reinterpret_cast<float2*>(dst)[2] = make_float2(r4, r5);
    }
}

extern "C" void kernel_launch(void* const* d_in, const int* in_sizes, int n_in,
                              void* d_out, int out_size)
{
    const float* x    = (const float*)d_in[0];
    const float* wgt  = (const float*)d_in[1];
    const float* bias = (const float*)d_in[2];
    float* out        = (float*)d_out;

    cudaFuncSetAttribute(lc2d_kernel,
                         cudaFuncAttributeMaxDynamicSharedMemorySize,
                         SMEM_BYTES);

    dim3 grid(504 / TW, 504 / TH);   // 42 x 126 = 5292 CTAs
    lc2d_kernel<<<grid, 512, SMEM_BYTES>>>(x, wgt, bias, out);
}

// round 5
// speedup vs baseline: 2.2678x; 1.1517x over previous
#include <cuda_runtime.h>

// Locally connected 2D:
//   y[n,h,w] = relu( sum_{i,j} x[n,h+i,w+j] * W[h,w,i,j] + b[h,w] )
// N=64, H_IN=W_IN=512, K=9, H_OUT=W_OUT=504.
//
// CTA: 512 threads = 16 warps = 4 h-rows x 2 n-halves x 2 w-halves.
// Tile: 4h x 12w x 64n (exact: 504 = 42*12 = 126*4). Lanes carry batch n,
// so weight LDS is warp-uniform broadcast. x staged [r][n][c], col pitch 20;
// sliding window = 4x LDS.128. The window offset (0 for w-half 0, 2 for
// w-half 1) is a TEMPLATE parameter so all window indices are compile-time
// (round-4's runtime index forced select-tree/local-mem traffic: alu=51%).

#define TW 12            // w outputs per CTA
#define WH 6             // w outputs per thread (w-half)
#define TH 4             // h rows per CTA
#define XR (TH + 8)      // 12 x rows staged
#define CP 20            // x cols staged per n (col pitch, floats)
#define RSTRIDE (64 * CP + 4)   // 1284 floats; +4 pad de-conflicts staging STS
#define WROW 12          // 9 taps padded to 12 floats (48B, 16B-aligned)
#define PIX (TH * TW)    // 48 pixels per CTA

// smem (floats): XS[XR][RSTRIDE] = 15408 ; WS[PIX][9*WROW] = 5184
#define XS_OFF 0
#define WS_OFF (XR * RSTRIDE)                 // 15408
#define SMEM_FLOATS (WS_OFF + PIX * 9 * WROW) // 20592
#define SMEM_BYTES (SMEM_FLOATS * 4)          // 82368

template<int XOFF>
__device__ __forceinline__
void lc2d_compute(const float* __restrict__ XS, const float* __restrict__ wbase,
                  const float* __restrict__ bp, float* __restrict__ dst,
                  int hl, int n)
{
    float acc[WH];
#pragma unroll
    for (int o = 0; o < WH; o++) acc[o] = 0.0f;

#pragma unroll
    for (int i = 0; i < 9; i++) {
        const int r = hl + i;
        // 16-col window via 4x LDS.128; XOFF=0 -> cols 0..15, XOFF=2 -> 4..19
        const float* xrow = XS + r * RSTRIDE + n * CP + (XOFF * 2);
        float4 X0 = reinterpret_cast<const float4*>(xrow)[0];
        float4 X1 = reinterpret_cast<const float4*>(xrow)[1];
        float4 X2 = reinterpret_cast<const float4*>(xrow)[2];
        float4 X3 = reinterpret_cast<const float4*>(xrow)[3];
        const float xw[16] = { X0.x, X0.y, X0.z, X0.w,
                               X1.x, X1.y, X1.z, X1.w,
                               X2.x, X2.y, X2.z, X2.w,
                               X3.x, X3.y, X3.z, X3.w };

#pragma unroll
        for (int o = 0; o < WH; o++) {
            const float* wrow = wbase + o * (9 * WROW) + i * WROW;
            const float4 wa = reinterpret_cast<const float4*>(wrow)[0]; // broadcast
            const float4 wb = reinterpret_cast<const float4*>(wrow)[1]; // broadcast
            const float  w8 = wrow[8];
            float a = acc[o];
            a = fmaf(xw[XOFF + o + 0], wa.x, a);
            a = fmaf(xw[XOFF + o + 1], wa.y, a);
            a = fmaf(xw[XOFF + o + 2], wa.z, a);
            a = fmaf(xw[XOFF + o + 3], wa.w, a);
            a = fmaf(xw[XOFF + o + 4], wb.x, a);
            a = fmaf(xw[XOFF + o + 5], wb.y, a);
            a = fmaf(xw[XOFF + o + 6], wb.z, a);
            a = fmaf(xw[XOFF + o + 7], wb.w, a);
            a = fmaf(xw[XOFF + o + 8], w8,   a);
            acc[o] = a;
        }
    }

    // bias + relu + direct store (3x STG.64)
    float r0 = fmaxf(acc[0] + __ldg(bp + 0), 0.0f);
    float r1 = fmaxf(acc[1] + __ldg(bp + 1), 0.0f);
    float r2 = fmaxf(acc[2] + __ldg(bp + 2), 0.0f);
    float r3 = fmaxf(acc[3] + __ldg(bp + 3), 0.0f);
    float r4 = fmaxf(acc[4] + __ldg(bp + 4), 0.0f);
    float r5 = fmaxf(acc[5] + __ldg(bp + 5), 0.0f);
    reinterpret_cast<float2*>(dst)[0] = make_float2(r0, r1);
    reinterpret_cast<float2*>(dst)[1] = make_float2(r2, r3);
    reinterpret_cast<float2*>(dst)[2] = make_float2(r4, r5);
}

__global__ __launch_bounds__(512, 2)
void lc2d_kernel(const float* __restrict__ x,
                 const float* __restrict__ wgt,
                 const float* __restrict__ bias,
                 float* __restrict__ out)
{
    extern __shared__ float sm[];
    float* XS = sm + XS_OFF;
    float* WS = sm + WS_OFF;

    const int tid  = threadIdx.x;
    const int lane = tid & 31;
    const int warp = tid >> 5;

    const int w0 = blockIdx.x * TW;   // 0..492
    const int h0 = blockIdx.y * TH;   // 0..500

    // ---- stage x: x[n, h0+r, w0+4c4..+3] -> XS[r*RSTRIDE + n*CP + 4c4] ----
    {
        const int n = tid >> 3;        // 0..63
        const int s = tid & 7;
        const float* src = x + (size_t)n * (512 * 512) + (size_t)h0 * 512 + w0;
        float* dstn = XS + n * CP;
#pragma unroll
        for (int k = 0; k < 8; k++) {
            int m = s + 8 * k;         // 0..63
            if (m < 60) {
                int r  = m / 5;
                int c4 = m - r * 5;
                float4 v = *reinterpret_cast<const float4*>(src + r * 512 + c4 * 4);
                *reinterpret_cast<float4*>(dstn + r * RSTRIDE + c4 * 4) = v;
            }
        }
    }

    // ---- stage weights: W[h0+hl, w0+o, i, j] -> WS[pix*108 + i*12 + j] ----
    {
        for (int t = tid; t < PIX * 81; t += 512) {   // 8 iterations
            int pix = t / 81;
            int q   = t - pix * 81;
            int i   = q / 9;
            int j   = q - i * 9;
            int hl  = pix / TW;
            int o   = pix - hl * TW;
            WS[pix * (9 * WROW) + i * WROW + j] =
                wgt[((size_t)(h0 + hl) * 504 + (w0 + o)) * 81 + q];
        }
    }

    __syncthreads();

    // ---- compute: warp = (hl, nh, wh); lane = n within half ----
    const int hl = warp >> 2;          // 0..3
    const int nh = (warp >> 1) & 1;    // 0..1
    const int wh = warp & 1;           // 0..1
    const int n  = nh * 32 + lane;
    const int h  = h0 + hl;
    const int cbase = wh * WH;         // 0 or 6

    const float* wbase = &WS[(hl * TW + cbase) * (9 * WROW)];
    const float* bp    = bias + (size_t)h * 504 + w0 + cbase;
    float*       dst   = out + ((size_t)n * 504 + h) * 504 + w0 + cbase;

    if (wh == 0) lc2d_compute<0>(XS, wbase, bp, dst, hl, n);
    else         lc2d_compute<2>(XS, wbase, bp, dst, hl, n);
}

extern "C" void kernel_launch(void* const* d_in, const int* in_sizes, int n_in,
                              void* d_out, int out_size)
{
    const float* x    = (const float*)d_in[0];
    const float* wgt  = (const float*)d_in[1];
    const float* bias = (const float*)d_in[2];
    float* out        = (float*)d_out;

    cudaFuncSetAttribute(lc2d_kernel,
                         cudaFuncAttributeMaxDynamicSharedMemorySize,
                         SMEM_BYTES);

    dim3 grid(504 / TW, 504 / TH);   // 42 x 126 = 5292 CTAs
    lc2d_kernel<<<grid, 512, SMEM_BYTES>>>(x, wgt, bias, out);
}

// round 6
// speedup vs baseline: 2.3549x; 1.0384x over previous
#include <cuda_runtime.h>

// Locally connected 2D:
//   y[n,h,w] = relu( sum_{i,j} x[n,h+i,w+j] * W[h,w,i,j] + b[h,w] )
// N=64, H_IN=W_IN=512, K=9, H_OUT=W_OUT=504.
//
// CTA: 512 threads = 16 warps = 4 h-rows x 2 n-halves x 2 w-halves.
// Tile: 4h x 12w x 64n (exact: 504 = 42*12 = 126*4). Lanes carry batch n ->
// weight LDS is warp-uniform broadcast. L1-wavefront diet vs round 5:
//   - x window: exactly 14 cols via 3x LDS.128 + 1x LDS.64 (was 4x LDS.128)
//   - weights packed [hl][i][wh][half][28]: 27 contiguous floats per half
//     (3 outputs x 9 taps) -> 7x LDS.128 per half, 14 total per iter (was 18
//     loads incl. 6 scalar). All indices compile-time (template on w-half).

#define TW 12            // w outputs per CTA
#define WH 6             // w outputs per thread (w-half)
#define TH 4             // h rows per CTA
#define XR (TH + 8)      // 12 x rows staged
#define CP 20            // x cols staged per n (col pitch, floats)
#define RSTRIDE (64 * CP + 4)   // 1284 floats; +4 pad de-conflicts staging STS
#define PIX (TH * TW)    // 48 pixels per CTA

// smem (floats):
//   XS[XR][RSTRIDE]            = 15408
//   WS[4][9][2][2][28]         =  4032   (27 weights + 1 pad per half-row)
#define XS_OFF 0
#define WS_OFF (XR * RSTRIDE)                  // 15408
#define SMEM_FLOATS (WS_OFF + 4 * 9 * 2 * 2 * 28)  // 19440
#define SMEM_BYTES (SMEM_FLOATS * 4)           // 77760

template<int WHI>   // w-half index: 0 or 1
__device__ __forceinline__
void lc2d_compute(const float* __restrict__ XS, const float* __restrict__ WS,
                  const float* __restrict__ bp, float* __restrict__ dst,
                  int hl, int n)
{
    float acc[WH];
#pragma unroll
    for (int o = 0; o < WH; o++) acc[o] = 0.0f;

#pragma unroll
    for (int i = 0; i < 9; i++) {
        const int r = hl + i;
        // window cols (global): WHI=0 -> 0..13 ; WHI=1 -> 6..19. xw[t] = col base+t.
        const float* xrow = XS + r * RSTRIDE + n * CP + (WHI ? 6 : 0);
        float xw[14];
        if (WHI == 0) {
            float4 a = *reinterpret_cast<const float4*>(xrow + 0);
            float4 b = *reinterpret_cast<const float4*>(xrow + 4);
            float4 c = *reinterpret_cast<const float4*>(xrow + 8);
            float2 d = *reinterpret_cast<const float2*>(xrow + 12);
            xw[0]=a.x; xw[1]=a.y; xw[2]=a.z; xw[3]=a.w;
            xw[4]=b.x; xw[5]=b.y; xw[6]=b.z; xw[7]=b.w;
            xw[8]=c.x; xw[9]=c.y; xw[10]=c.z; xw[11]=c.w;
            xw[12]=d.x; xw[13]=d.y;
        } else {
            float2 d = *reinterpret_cast<const float2*>(xrow + 0);
            float4 a = *reinterpret_cast<const float4*>(xrow + 2);
            float4 b = *reinterpret_cast<const float4*>(xrow + 6);
            float4 c = *reinterpret_cast<const float4*>(xrow + 10);
            xw[0]=d.x; xw[1]=d.y;
            xw[2]=a.x; xw[3]=a.y; xw[4]=a.z; xw[5]=a.w;
            xw[6]=b.x; xw[7]=b.y; xw[8]=b.z; xw[9]=b.w;
            xw[10]=c.x; xw[11]=c.y; xw[12]=c.z; xw[13]=c.w;
        }

        // weights for this (hl, i, wh): 2 halves of 27 floats (+1 pad) each
        const float* wrow = WS + (((hl * 9 + i) * 2 + WHI) * 2) * 28;

#pragma unroll
        for (int half = 0; half < 2; half++) {
            const float* wb = wrow + half * 28;
            float w[28];
#pragma unroll
            for (int k = 0; k < 7; k++) {
                float4 v = *reinterpret_cast<const float4*>(wb + 4 * k);  // broadcast
                w[4*k+0]=v.x; w[4*k+1]=v.y; w[4*k+2]=v.z; w[4*k+3]=v.w;
            }
#pragma unroll
            for (int ol = 0; ol < 3; ol++) {
                const int o = half * 3 + ol;
                float a = acc[o];
#pragma unroll
                for (int j = 0; j < 9; j++)
                    a = fmaf(xw[o + j], w[ol * 9 + j], a);
                acc[o] = a;
            }
        }
    }

    // bias + relu + direct store (3x STG.64)
    float r0 = fmaxf(acc[0] + __ldg(bp + 0), 0.0f);
    float r1 = fmaxf(acc[1] + __ldg(bp + 1), 0.0f);
    float r2 = fmaxf(acc[2] + __ldg(bp + 2), 0.0f);
    float r3 = fmaxf(acc[3] + __ldg(bp + 3), 0.0f);
    float r4 = fmaxf(acc[4] + __ldg(bp + 4), 0.0f);
    float r5 = fmaxf(acc[5] + __ldg(bp + 5), 0.0f);
    reinterpret_cast<float2*>(dst)[0] = make_float2(r0, r1);
    reinterpret_cast<float2*>(dst)[1] = make_float2(r2, r3);
    reinterpret_cast<float2*>(dst)[2] = make_float2(r4, r5);
}

__global__ __launch_bounds__(512, 2)
void lc2d_kernel(const float* __restrict__ x,
                 const float* __restrict__ wgt,
                 const float* __restrict__ bias,
                 float* __restrict__ out)
{
    extern __shared__ float sm[];
    float* XS = sm + XS_OFF;
    float* WS = sm + WS_OFF;

    const int tid  = threadIdx.x;
    const int lane = tid & 31;
    const int warp = tid >> 5;

    const int w0 = blockIdx.x * TW;   // 0..492
    const int h0 = blockIdx.y * TH;   // 0..500

    // ---- stage x: x[n, h0+r, w0+4c4..+3] -> XS[r*RSTRIDE + n*CP + 4c4] ----
    {
        const int nn = tid >> 3;       // 0..63
        const int s  = tid & 7;
        const float* src = x + (size_t)nn * (512 * 512) + (size_t)h0 * 512 + w0;
        float* dstn = XS + nn * CP;
#pragma unroll
        for (int k = 0; k < 8; k++) {
            int m = s + 8 * k;         // 0..63
            if (m < 60) {
                int r  = m / 5;
                int c4 = m - r * 5;
                float4 v = *reinterpret_cast<const float4*>(src + r * 512 + c4 * 4);
                *reinterpret_cast<float4*>(dstn + r * RSTRIDE + c4 * 4) = v;
            }
        }
    }

    // ---- stage weights: W[h0+hl, w0+o, i, j] -> WS[hl][i][wh][half][within*9+j]
    {
        for (int t = tid; t < PIX * 81; t += 512) {   // 8 iterations (48*81=3888)
            int pix = t / 81;          // hl*12 + o
            int q   = t - pix * 81;
            int i   = q / 9;
            int j   = q - i * 9;
            int hl  = pix / TW;
            int o   = pix - hl * TW;   // 0..11
            int wh  = o / 6;
            int ol  = o - wh * 6;      // 0..5
            int hf  = ol / 3;
            int wi  = ol - hf * 3;     // 0..2
            WS[(((hl * 9 + i) * 2 + wh) * 2 + hf) * 28 + wi * 9 + j] =
                wgt[((size_t)(h0 + hl) * 504 + (w0 + o)) * 81 + q];
        }
    }

    __syncthreads();

    // ---- compute: warp = (hl, nh, wh); lane = n within half ----
    const int hl = warp >> 2;          // 0..3
    const int nh = (warp >> 1) & 1;    // 0..1
    const int wh = warp & 1;           // 0..1
    const int n  = nh * 32 + lane;
    const int h  = h0 + hl;
    const int cbase = wh * WH;         // 0 or 6

    const float* bp  = bias + (size_t)h * 504 + w0 + cbase;
    float*       dst = out + ((size_t)n * 504 + h) * 504 + w0 + cbase;

    if (wh == 0) lc2d_compute<0>(XS, WS, bp, dst, hl, n);
    else         lc2d_compute<1>(XS, WS, bp, dst, hl, n);
}

extern "C" void kernel_launch(void* const* d_in, const int* in_sizes, int n_in,
                              void* d_out, int out_size)
{
    const float* x    = (const float*)d_in[0];
    const float* wgt  = (const float*)d_in[1];
    const float* bias = (const float*)d_in[2];
    float* out        = (float*)d_out;

    cudaFuncSetAttribute(lc2d_kernel,
                         cudaFuncAttributeMaxDynamicSharedMemorySize,
                         SMEM_BYTES);

    dim3 grid(504 / TW, 504 / TH);   // 42 x 126 = 5292 CTAs
    lc2d_kernel<<<grid, 512, SMEM_BYTES>>>(x, wgt, bias, out);
}